// round 2
// baseline (speedup 1.0000x reference)
#include <cuda_runtime.h>
#include <math.h>

// Problem constants (fixed shapes)
constexpr int N_   = 50000;
constexpr int E_   = 400000;
constexpr int ETOT = E_ + N_;   // edges + self loops

// ---------------- scratch (device globals; no allocations allowed) --------
__device__ __align__(16) float g_h1[N_ * 256];     // layer1 features [N,4,64]
__device__ __align__(16) float g_asrc1[N_ * 4];
__device__ __align__(16) float g_adst1[N_ * 4];
__device__ __align__(16) float g_emax1[N_ * 4];
__device__ __align__(16) float g_denom1[N_ * 4];
__device__ __align__(16) float g_e1[ETOT * 4];     // per-edge logits layer1
__device__ __align__(16) float g_agg1[N_ * 256];
__device__ __align__(16) float g_x2[N_ * 64];      // layer1 output / layer2 input
__device__ __align__(16) float g_h2[N_ * 64];
__device__ float g_asrc2[N_];
__device__ float g_adst2[N_];
__device__ float g_emax2[N_];
__device__ float g_denom2[N_];
__device__ float g_e2[ETOT];
__device__ __align__(16) float g_agg2[N_ * 64];
__device__ int   g_is64;       // edge_index dtype flag (1 = int64, 0 = int32)

// ---------------- helpers -------------------------------------------------
__device__ __forceinline__ float lrelu(float x) { return x > 0.f ? x : 0.2f * x; }
__device__ __forceinline__ float eluf(float x)  { return x > 0.f ? x : expm1f(x); }

__device__ __forceinline__ void atomicMaxF(float* a, float v) {
    // ordered-int trick; correct for mixed signs when initialized to a very
    // negative value.
    if (v >= 0.f) atomicMax((int*)a, __float_as_int(v));
    else          atomicMin((unsigned int*)a, __float_as_uint(v));
}

__device__ __forceinline__ void red4(float* a, float4 v) {
    asm volatile("red.global.add.v4.f32 [%0], {%1,%2,%3,%4};"
                 :: "l"(a), "f"(v.x), "f"(v.y), "f"(v.z), "f"(v.w) : "memory");
}

__device__ __forceinline__ int2 load_edge(const void* ei, int e) {
    int2 r;
    if (g_is64) {
        const long long* p = (const long long*)ei;
        r.x = (int)p[e];
        r.y = (int)p[E_ + e];
    } else {
        const int* p = (const int*)ei;
        r.x = p[e];
        r.y = p[E_ + e];
    }
    return r;
}

// ---------------- dtype detection ----------------------------------------
__global__ void k_detect(const unsigned int* __restrict__ ei) {
    if (blockIdx.x == 0 && threadIdx.x == 0) {
        // If int64, every high 32-bit word is 0 (values in [0, 50000)).
        int ok = 1;
        for (int i = 0; i < 32; i++)
            if (ei[2 * i + 1] != 0u) { ok = 0; break; }
        g_is64 = ok;
    }
}

// ---------------- init (merged) -------------------------------------------
__global__ void k_init() {
    int stride = gridDim.x * blockDim.x;
    int i0 = blockIdx.x * blockDim.x + threadIdx.x;
    for (int j = i0; j < N_ * 256; j += stride) g_agg1[j] = 0.f;
    for (int j = i0; j < N_ * 64;  j += stride) g_agg2[j] = 0.f;
    for (int j = i0; j < N_ * 4;   j += stride) { g_emax1[j] = -1e30f; g_denom1[j] = 0.f; }
    for (int j = i0; j < N_;       j += stride) { g_emax2[j] = -1e30f; g_denom2[j] = 0.f; }
}

// ---------------- layer 1: GEMM + attention logits ------------------------
// x [N,16] @ W1 [16,256] -> h1 [N,256]; a_src/a_dst [N,4] reductions.
__global__ void k_gemm1(const float* __restrict__ x, const float* __restrict__ W,
                        const float* __restrict__ as, const float* __restrict__ ad) {
    __shared__ float Ws[16 * 256];
    __shared__ float xs[16 * 16];
    __shared__ float rs[16 * 4];
    __shared__ float rd[16 * 4];
    int t = threadIdx.x;                 // 256 threads = output column
    for (int i = t; i < 4096; i += 256) Ws[i] = W[i];
    int nb = blockIdx.x * 16;
    {
        int n = nb + (t >> 4);
        xs[t] = (n < N_) ? x[n * 16 + (t & 15)] : 0.f;
    }
    if (t < 64) { rs[t] = 0.f; rd[t] = 0.f; }
    float a_s = as[t], a_d = ad[t];
    __syncthreads();
    int head = t >> 6;
    for (int i = 0; i < 16; i++) {
        int n = nb + i;
        if (n >= N_) break;
        float acc = 0.f;
        #pragma unroll
        for (int k = 0; k < 16; k++) acc = fmaf(xs[i * 16 + k], Ws[k * 256 + t], acc);
        g_h1[n * 256 + t] = acc;
        float ps = acc * a_s, pd = acc * a_d;
        #pragma unroll
        for (int o = 16; o > 0; o >>= 1) {
            ps += __shfl_down_sync(0xffffffffu, ps, o);
            pd += __shfl_down_sync(0xffffffffu, pd, o);
        }
        if ((t & 31) == 0) {   // 2 warps per head contribute
            atomicAdd(&rs[i * 4 + head], ps);
            atomicAdd(&rd[i * 4 + head], pd);
        }
    }
    __syncthreads();
    if (t < 64) {
        int n = nb + (t >> 2);
        if (n < N_) {
            g_asrc1[n * 4 + (t & 3)] = rs[t];
            g_adst1[n * 4 + (t & 3)] = rd[t];
        }
    }
}

// ---------------- layer 2: GEMM + attention logits ------------------------
// g_x2 [N,64] @ W2 [64,64] -> h2 [N,64]; scalar a_src/a_dst.
__global__ void k_gemm2(const float* __restrict__ W,
                        const float* __restrict__ as, const float* __restrict__ ad) {
    __shared__ float Ws[64 * 64];
    __shared__ float xs[16 * 65];   // padded to kill bank conflicts
    __shared__ float rs[16];
    __shared__ float rd[16];
    int t = threadIdx.x;
    int col = t & 63;
    int g = t >> 6;                  // 4 node groups
    for (int i = t; i < 4096; i += 256) Ws[i] = W[i];
    int nb = blockIdx.x * 16;
    for (int i = t; i < 1024; i += 256) {
        int n = nb + (i >> 6);
        xs[(i >> 6) * 65 + (i & 63)] = (n < N_) ? g_x2[n * 64 + (i & 63)] : 0.f;
    }
    if (t < 16) { rs[t] = 0.f; rd[t] = 0.f; }
    float a_s = as[col], a_d = ad[col];
    __syncthreads();
    for (int it = 0; it < 4; it++) {
        int i = it * 4 + g;
        int n = nb + i;
        float acc = 0.f;
        #pragma unroll
        for (int k = 0; k < 64; k++) acc = fmaf(xs[i * 65 + k], Ws[k * 64 + col], acc);
        if (n < N_) g_h2[n * 64 + col] = acc;
        float ps = acc * a_s, pd = acc * a_d;
        #pragma unroll
        for (int o = 16; o > 0; o >>= 1) {
            ps += __shfl_down_sync(0xffffffffu, ps, o);
            pd += __shfl_down_sync(0xffffffffu, pd, o);
        }
        if ((t & 31) == 0 && n < N_) {
            atomicAdd(&rs[i], ps);
            atomicAdd(&rd[i], pd);
        }
    }
    __syncthreads();
    if (t < 16) {
        int n = nb + t;
        if (n < N_) { g_asrc2[n] = rs[t]; g_adst2[n] = rd[t]; }
    }
}

// ---------------- edge pass A: logits + segment max -----------------------
__global__ void k_emax1(const void* __restrict__ ei) {
    int e = blockIdx.x * blockDim.x + threadIdx.x;
    if (e >= ETOT) return;
    int s, d;
    if (e < E_) { int2 sd = load_edge(ei, e); s = sd.x; d = sd.y; }
    else        { s = d = e - E_; }
    float4 a = *(const float4*)&g_asrc1[s * 4];
    float4 b = *(const float4*)&g_adst1[d * 4];
    float4 ev = make_float4(lrelu(a.x + b.x), lrelu(a.y + b.y),
                            lrelu(a.z + b.z), lrelu(a.w + b.w));
    *(float4*)&g_e1[e * 4] = ev;
    atomicMaxF(&g_emax1[d * 4 + 0], ev.x);
    atomicMaxF(&g_emax1[d * 4 + 1], ev.y);
    atomicMaxF(&g_emax1[d * 4 + 2], ev.z);
    atomicMaxF(&g_emax1[d * 4 + 3], ev.w);
}

__global__ void k_emax2(const void* __restrict__ ei) {
    int e = blockIdx.x * blockDim.x + threadIdx.x;
    if (e >= ETOT) return;
    int s, d;
    if (e < E_) { int2 sd = load_edge(ei, e); s = sd.x; d = sd.y; }
    else        { s = d = e - E_; }
    float ev = lrelu(g_asrc2[s] + g_adst2[d]);
    g_e2[e] = ev;
    atomicMaxF(&g_emax2[d], ev);
}

// ---------------- edge pass B: fused exp + denom + weighted aggregate -----
// Softmax division deferred to finalize: agg[dst] += exp(e - emax[dst]) * h[src]
// Layer 1: one warp per edge, 256 floats (4 heads x 64) -> 8 floats/lane.
__global__ void k_eagg1(const void* __restrict__ ei) {
    int gt = blockIdx.x * blockDim.x + threadIdx.x;
    int e = gt >> 5;
    int lane = gt & 31;
    if (e >= ETOT) return;
    int s, d;
    if (e < E_) { int2 sd = load_edge(ei, e); s = sd.x; d = sd.y; }
    else        { s = d = e - E_; }
    float ex = 0.f;
    if (lane < 4) {
        float ev = g_e1[e * 4 + lane];
        ex = __expf(ev - g_emax1[d * 4 + lane]);
        atomicAdd(&g_denom1[d * 4 + lane], ex);
    }
    float exh = __shfl_sync(0xffffffffu, ex, lane >> 3);  // head = lane/8
    const float4* hp = (const float4*)&g_h1[s * 256 + lane * 8];
    float4 v0 = hp[0], v1 = hp[1];
    v0.x *= exh; v0.y *= exh; v0.z *= exh; v0.w *= exh;
    v1.x *= exh; v1.y *= exh; v1.z *= exh; v1.w *= exh;
    float* ap = &g_agg1[d * 256 + lane * 8];
    red4(ap, v0);
    red4(ap + 4, v1);
}

// Layer 2: 16 threads per edge (64 floats -> float4/lane), 2 edges per warp.
__global__ void k_eagg2(const void* __restrict__ ei) {
    int gt = blockIdx.x * blockDim.x + threadIdx.x;
    int e = gt >> 4;
    int l = gt & 15;
    if (e >= ETOT) return;
    int s, d;
    if (e < E_) { int2 sd = load_edge(ei, e); s = sd.x; d = sd.y; }
    else        { s = d = e - E_; }
    float ex = 0.f;
    if (l == 0) {
        ex = __expf(g_e2[e] - g_emax2[d]);
        atomicAdd(&g_denom2[d], ex);
    }
    ex = __shfl_sync(0xffffffffu, ex, 0, 16);  // broadcast within 16-group
    float4 v = *(const float4*)&g_h2[s * 64 + l * 4];
    v.x *= ex; v.y *= ex; v.z *= ex; v.w *= ex;
    red4(&g_agg2[d * 64 + l * 4], v);
}

// ---------------- finalize: divide, mean heads, bias, ELU -----------------
__global__ void k_fin1(const float* __restrict__ b1) {
    int idx = blockIdx.x * blockDim.x + threadIdx.x;
    if (idx >= N_ * 64) return;
    int n = idx >> 6, c = idx & 63;
    float sum = 0.f;
    #pragma unroll
    for (int h = 0; h < 4; h++)
        sum += g_agg1[n * 256 + h * 64 + c] / (g_denom1[n * 4 + h] + 1e-16f);
    g_x2[idx] = eluf(0.25f * sum + b1[c]);
}

__global__ void k_fin2(const float* __restrict__ b2, float* __restrict__ out) {
    int idx = blockIdx.x * blockDim.x + threadIdx.x;
    if (idx >= N_ * 64) return;
    int n = idx >> 6, c = idx & 63;
    out[idx] = eluf(g_agg2[idx] / (g_denom2[n] + 1e-16f) + b2[c]);
}

// ---------------- launch --------------------------------------------------
extern "C" void kernel_launch(void* const* d_in, const int* in_sizes, int n_in,
                              void* d_out, int out_size) {
    const float* x   = (const float*)d_in[0];
    const void*  ei  = d_in[1];
    const float* W1  = (const float*)d_in[2];
    const float* as1 = (const float*)d_in[3];
    const float* ad1 = (const float*)d_in[4];
    const float* b1  = (const float*)d_in[5];
    const float* W2  = (const float*)d_in[6];
    const float* as2 = (const float*)d_in[7];
    const float* ad2 = (const float*)d_in[8];
    const float* b2  = (const float*)d_in[9];
    float* out = (float*)d_out;

    k_detect<<<1, 32>>>((const unsigned int*)ei);
    k_init<<<1280, 256>>>();

    // Layer 1
    k_gemm1<<<(N_ + 15) / 16, 256>>>(x, W1, as1, ad1);
    k_emax1<<<(ETOT + 255) / 256, 256>>>(ei);
    k_eagg1<<<(ETOT * 32 + 255) / 256, 256>>>(ei);
    k_fin1<<<(N_ * 64 + 255) / 256, 256>>>(b1);

    // Layer 2
    k_gemm2<<<(N_ + 15) / 16, 256>>>(W2, as2, ad2);
    k_emax2<<<(ETOT + 255) / 256, 256>>>(ei);
    k_eagg2<<<(ETOT * 16 + 255) / 256, 256>>>(ei);
    k_fin2<<<(N_ * 64 + 255) / 256, 256>>>(b2, out);
}

// round 3
// speedup vs baseline: 1.2394x; 1.2394x over previous
#include <cuda_runtime.h>
#include <math.h>

constexpr int N_   = 50000;
constexpr int E_   = 400000;
constexpr int ETOT = E_ + N_;   // edges + self loops

// ---------------- scratch ---------------------------------------------------
__device__ __align__(16) float g_h1[N_ * 256];   // layer1 features [N,4,64]
__device__ __align__(16) float g_asrc1[N_ * 4];
__device__ __align__(16) float g_adst1[N_ * 4];
__device__ __align__(16) float g_x2[N_ * 64];    // layer1 out / layer2 in
__device__ __align__(16) float g_h2[N_ * 64];
__device__ float g_asrc2[N_];
__device__ float g_adst2[N_];
__device__ int   g_deg[N_];
__device__ int   g_rp[N_ + 1];
__device__ int   g_cursor[N_];
__device__ int   g_csr_src[ETOT];
__device__ int   g_is64;

// ---------------- helpers ---------------------------------------------------
__device__ __forceinline__ float lrelu(float x) { return x > 0.f ? x : 0.2f * x; }
__device__ __forceinline__ float eluf(float x)  { return x > 0.f ? x : expm1f(x); }

__device__ __forceinline__ int2 load_edge(const void* ei, int e) {
    int2 r;
    if (g_is64) {
        const long long* p = (const long long*)ei;
        r.x = (int)p[e]; r.y = (int)p[E_ + e];
    } else {
        const int* p = (const int*)ei;
        r.x = p[e]; r.y = p[E_ + e];
    }
    return r;
}

// ---------------- dtype detect + degree init -------------------------------
__global__ void k_detect(const unsigned int* __restrict__ ei) {
    if (threadIdx.x == 0) {
        int ok = 1;
        for (int i = 0; i < 32; i++)
            if (ei[2 * i + 1] != 0u) { ok = 0; break; }
        g_is64 = ok;
    }
}

__global__ void k_deginit() {
    int i = blockIdx.x * blockDim.x + threadIdx.x;
    if (i < N_) g_deg[i] = 1;          // self loop
}

__global__ void k_hist(const void* __restrict__ ei) {
    int e = blockIdx.x * blockDim.x + threadIdx.x;
    if (e >= E_) return;
    int2 sd = load_edge(ei, e);
    atomicAdd(&g_deg[sd.y], 1);
}

// single-block exclusive scan over g_deg -> g_rp, g_cursor
__global__ void k_scan() {
    __shared__ int sm[1024];
    __shared__ int s_off;
    int t = threadIdx.x;
    if (t == 0) s_off = 0;
    __syncthreads();
    for (int base = 0; base < N_; base += 1024) {
        int v = (base + t < N_) ? g_deg[base + t] : 0;
        sm[t] = v; __syncthreads();
        int x = v;
        for (int o = 1; o < 1024; o <<= 1) {
            int add = (t >= o) ? sm[t - o] : 0;
            __syncthreads();
            x += add; sm[t] = x;
            __syncthreads();
        }
        int off = s_off;
        if (base + t < N_) {
            int excl = off + x - v;
            g_rp[base + t] = excl;
            g_cursor[base + t] = excl;
        }
        __syncthreads();
        if (t == 1023) s_off = off + sm[1023];
        __syncthreads();
    }
    if (t == 0) g_rp[N_] = s_off;
}

__global__ void k_scatter(const void* __restrict__ ei) {
    int e = blockIdx.x * blockDim.x + threadIdx.x;
    if (e >= ETOT) return;
    int s, d;
    if (e < E_) { int2 sd = load_edge(ei, e); s = sd.x; d = sd.y; }
    else        { s = d = e - E_; }
    int pos = atomicAdd(&g_cursor[d], 1);
    g_csr_src[pos] = s;
}

// ---------------- layer 1: GEMM + attention logits -------------------------
__global__ void k_gemm1(const float* __restrict__ x, const float* __restrict__ W,
                        const float* __restrict__ as, const float* __restrict__ ad) {
    __shared__ float Ws[16 * 256];
    __shared__ float xs[16 * 16];
    __shared__ float rs[16 * 4];
    __shared__ float rd[16 * 4];
    int t = threadIdx.x;
    for (int i = t; i < 4096; i += 256) Ws[i] = W[i];
    int nb = blockIdx.x * 16;
    {
        int n = nb + (t >> 4);
        xs[t] = (n < N_) ? x[n * 16 + (t & 15)] : 0.f;
    }
    if (t < 64) { rs[t] = 0.f; rd[t] = 0.f; }
    float a_s = as[t], a_d = ad[t];
    __syncthreads();
    int head = t >> 6;
    for (int i = 0; i < 16; i++) {
        int n = nb + i;
        if (n >= N_) break;
        float acc = 0.f;
        #pragma unroll
        for (int k = 0; k < 16; k++) acc = fmaf(xs[i * 16 + k], Ws[k * 256 + t], acc);
        g_h1[n * 256 + t] = acc;
        float ps = acc * a_s, pd = acc * a_d;
        #pragma unroll
        for (int o = 16; o > 0; o >>= 1) {
            ps += __shfl_down_sync(0xffffffffu, ps, o);
            pd += __shfl_down_sync(0xffffffffu, pd, o);
        }
        if ((t & 31) == 0) {
            atomicAdd(&rs[i * 4 + head], ps);
            atomicAdd(&rd[i * 4 + head], pd);
        }
    }
    __syncthreads();
    if (t < 64) {
        int n = nb + (t >> 2);
        if (n < N_) {
            g_asrc1[n * 4 + (t & 3)] = rs[t];
            g_adst1[n * 4 + (t & 3)] = rd[t];
        }
    }
}

// ---------------- layer 2: GEMM + attention logits -------------------------
__global__ void k_gemm2(const float* __restrict__ W,
                        const float* __restrict__ as, const float* __restrict__ ad) {
    __shared__ float Ws[64 * 64];
    __shared__ float xs[16 * 65];
    __shared__ float rs[16];
    __shared__ float rd[16];
    int t = threadIdx.x;
    int col = t & 63;
    int g = t >> 6;
    for (int i = t; i < 4096; i += 256) Ws[i] = W[i];
    int nb = blockIdx.x * 16;
    for (int i = t; i < 1024; i += 256) {
        int n = nb + (i >> 6);
        xs[(i >> 6) * 65 + (i & 63)] = (n < N_) ? g_x2[n * 64 + (i & 63)] : 0.f;
    }
    if (t < 16) { rs[t] = 0.f; rd[t] = 0.f; }
    float a_s = as[col], a_d = ad[col];
    __syncthreads();
    for (int it = 0; it < 4; it++) {
        int i = it * 4 + g;
        int n = nb + i;
        float acc = 0.f;
        #pragma unroll
        for (int k = 0; k < 64; k++) acc = fmaf(xs[i * 65 + k], Ws[k * 64 + col], acc);
        if (n < N_) g_h2[n * 64 + col] = acc;
        float ps = acc * a_s, pd = acc * a_d;
        #pragma unroll
        for (int o = 16; o > 0; o >>= 1) {
            ps += __shfl_down_sync(0xffffffffu, ps, o);
            pd += __shfl_down_sync(0xffffffffu, pd, o);
        }
        if ((t & 31) == 0 && n < N_) {
            atomicAdd(&rs[i], ps);
            atomicAdd(&rd[i], pd);
        }
    }
    __syncthreads();
    if (t < 16) {
        int n = nb + t;
        if (n < N_) { g_asrc2[n] = rs[t]; g_adst2[n] = rd[t]; }
    }
}

// ---------------- layer 1 fused softmax-aggregate (warp per dst) -----------
// out[d] = ELU( mean_h( sum_e ex_eh * h1[s_e,h,:] / (sum_e ex_eh + eps) ) + b1 )
__global__ void k_agg1(const float* __restrict__ b1) {
    __shared__ int   sm_s[8 * 32];
    __shared__ float4 sm_ex[8 * 32];
    int lane = threadIdx.x & 31;
    int w = threadIdx.x >> 5;
    int d = blockIdx.x * 8 + w;
    if (d >= N_) return;
    int rs = g_rp[d];
    int deg = g_rp[d + 1] - rs;
    float4 adst = *(const float4*)&g_adst1[d * 4];

    // pass A: per-head max over edges
    float4 m = make_float4(-1e30f, -1e30f, -1e30f, -1e30f);
    for (int base = 0; base < deg; base += 32) {
        int i = base + lane;
        if (i < deg) {
            int s = g_csr_src[rs + i];
            float4 a = *(const float4*)&g_asrc1[s * 4];
            m.x = fmaxf(m.x, lrelu(a.x + adst.x));
            m.y = fmaxf(m.y, lrelu(a.y + adst.y));
            m.z = fmaxf(m.z, lrelu(a.z + adst.z));
            m.w = fmaxf(m.w, lrelu(a.w + adst.w));
        }
    }
    #pragma unroll
    for (int o = 16; o > 0; o >>= 1) {
        m.x = fmaxf(m.x, __shfl_xor_sync(0xffffffffu, m.x, o));
        m.y = fmaxf(m.y, __shfl_xor_sync(0xffffffffu, m.y, o));
        m.z = fmaxf(m.z, __shfl_xor_sync(0xffffffffu, m.z, o));
        m.w = fmaxf(m.w, __shfl_xor_sync(0xffffffffu, m.w, o));
    }

    // pass B: exp, denom, weighted aggregate
    float4 den = make_float4(0.f, 0.f, 0.f, 0.f);
    float4 a0 = make_float4(0.f, 0.f, 0.f, 0.f);
    float4 a1 = make_float4(0.f, 0.f, 0.f, 0.f);
    int head = lane >> 3;
    for (int base = 0; base < deg; base += 32) {
        int i = base + lane;
        int s = -1;
        float4 ex = make_float4(0.f, 0.f, 0.f, 0.f);
        if (i < deg) {
            s = g_csr_src[rs + i];
            float4 a = *(const float4*)&g_asrc1[s * 4];
            ex.x = __expf(lrelu(a.x + adst.x) - m.x);
            ex.y = __expf(lrelu(a.y + adst.y) - m.y);
            ex.z = __expf(lrelu(a.z + adst.z) - m.z);
            ex.w = __expf(lrelu(a.w + adst.w) - m.w);
            den.x += ex.x; den.y += ex.y; den.z += ex.z; den.w += ex.w;
        }
        sm_s[w * 32 + lane] = s;
        sm_ex[w * 32 + lane] = ex;
        __syncwarp();
        int cnt = min(32, deg - base);
        const float* exb = (const float*)&sm_ex[w * 32];
        for (int j = 0; j < cnt; j++) {
            int sj = sm_s[w * 32 + j];
            float exj = exb[j * 4 + head];
            const float4* hp = (const float4*)&g_h1[sj * 256 + lane * 8];
            float4 v0 = hp[0], v1 = hp[1];
            a0.x = fmaf(exj, v0.x, a0.x); a0.y = fmaf(exj, v0.y, a0.y);
            a0.z = fmaf(exj, v0.z, a0.z); a0.w = fmaf(exj, v0.w, a0.w);
            a1.x = fmaf(exj, v1.x, a1.x); a1.y = fmaf(exj, v1.y, a1.y);
            a1.z = fmaf(exj, v1.z, a1.z); a1.w = fmaf(exj, v1.w, a1.w);
        }
        __syncwarp();
    }
    #pragma unroll
    for (int o = 16; o > 0; o >>= 1) {
        den.x += __shfl_xor_sync(0xffffffffu, den.x, o);
        den.y += __shfl_xor_sync(0xffffffffu, den.y, o);
        den.z += __shfl_xor_sync(0xffffffffu, den.z, o);
        den.w += __shfl_xor_sync(0xffffffffu, den.w, o);
    }
    float dh = (head == 0 ? den.x : head == 1 ? den.y : head == 2 ? den.z : den.w);
    float inv = 1.f / (dh + 1e-16f);
    a0.x *= inv; a0.y *= inv; a0.z *= inv; a0.w *= inv;
    a1.x *= inv; a1.y *= inv; a1.z *= inv; a1.w *= inv;
    // sum over heads: combine lanes {l, l+8, l+16, l+24}
    #pragma unroll
    for (int o = 8; o <= 16; o <<= 1) {
        a0.x += __shfl_xor_sync(0xffffffffu, a0.x, o);
        a0.y += __shfl_xor_sync(0xffffffffu, a0.y, o);
        a0.z += __shfl_xor_sync(0xffffffffu, a0.z, o);
        a0.w += __shfl_xor_sync(0xffffffffu, a0.w, o);
        a1.x += __shfl_xor_sync(0xffffffffu, a1.x, o);
        a1.y += __shfl_xor_sync(0xffffffffu, a1.y, o);
        a1.z += __shfl_xor_sync(0xffffffffu, a1.z, o);
        a1.w += __shfl_xor_sync(0xffffffffu, a1.w, o);
    }
    if (lane < 8) {
        int c = lane * 8;
        float* o = &g_x2[d * 64 + c];
        o[0] = eluf(0.25f * a0.x + b1[c + 0]);
        o[1] = eluf(0.25f * a0.y + b1[c + 1]);
        o[2] = eluf(0.25f * a0.z + b1[c + 2]);
        o[3] = eluf(0.25f * a0.w + b1[c + 3]);
        o[4] = eluf(0.25f * a1.x + b1[c + 4]);
        o[5] = eluf(0.25f * a1.y + b1[c + 5]);
        o[6] = eluf(0.25f * a1.z + b1[c + 6]);
        o[7] = eluf(0.25f * a1.w + b1[c + 7]);
    }
}

// ---------------- layer 2 fused softmax-aggregate (warp per dst) -----------
__global__ void k_agg2(const float* __restrict__ b2, float* __restrict__ out) {
    __shared__ int   sm_s[8 * 32];
    __shared__ float sm_ex[8 * 32];
    int lane = threadIdx.x & 31;
    int w = threadIdx.x >> 5;
    int d = blockIdx.x * 8 + w;
    if (d >= N_) return;
    int rs = g_rp[d];
    int deg = g_rp[d + 1] - rs;
    float adst = g_adst2[d];

    float m = -1e30f;
    for (int base = 0; base < deg; base += 32) {
        int i = base + lane;
        if (i < deg) {
            int s = g_csr_src[rs + i];
            m = fmaxf(m, lrelu(g_asrc2[s] + adst));
        }
    }
    #pragma unroll
    for (int o = 16; o > 0; o >>= 1)
        m = fmaxf(m, __shfl_xor_sync(0xffffffffu, m, o));

    float den = 0.f;
    float2 acc = make_float2(0.f, 0.f);
    for (int base = 0; base < deg; base += 32) {
        int i = base + lane;
        int s = -1;
        float ex = 0.f;
        if (i < deg) {
            s = g_csr_src[rs + i];
            ex = __expf(lrelu(g_asrc2[s] + adst) - m);
            den += ex;
        }
        sm_s[w * 32 + lane] = s;
        sm_ex[w * 32 + lane] = ex;
        __syncwarp();
        int cnt = min(32, deg - base);
        for (int j = 0; j < cnt; j++) {
            int sj = sm_s[w * 32 + j];
            float exj = sm_ex[w * 32 + j];
            float2 v = *(const float2*)&g_h2[sj * 64 + lane * 2];
            acc.x = fmaf(exj, v.x, acc.x);
            acc.y = fmaf(exj, v.y, acc.y);
        }
        __syncwarp();
    }
    #pragma unroll
    for (int o = 16; o > 0; o >>= 1)
        den += __shfl_xor_sync(0xffffffffu, den, o);
    float inv = 1.f / (den + 1e-16f);
    int c = lane * 2;
    out[d * 64 + c + 0] = eluf(acc.x * inv + b2[c + 0]);
    out[d * 64 + c + 1] = eluf(acc.y * inv + b2[c + 1]);
}

// ---------------- launch ----------------------------------------------------
extern "C" void kernel_launch(void* const* d_in, const int* in_sizes, int n_in,
                              void* d_out, int out_size) {
    const float* x   = (const float*)d_in[0];
    const void*  ei  = d_in[1];
    const float* W1  = (const float*)d_in[2];
    const float* as1 = (const float*)d_in[3];
    const float* ad1 = (const float*)d_in[4];
    const float* b1  = (const float*)d_in[5];
    const float* W2  = (const float*)d_in[6];
    const float* as2 = (const float*)d_in[7];
    const float* ad2 = (const float*)d_in[8];
    const float* b2  = (const float*)d_in[9];
    float* out = (float*)d_out;

    k_detect<<<1, 32>>>((const unsigned int*)ei);
    k_deginit<<<(N_ + 255) / 256, 256>>>();
    k_hist<<<(E_ + 255) / 256, 256>>>(ei);
    k_scan<<<1, 1024>>>();
    k_scatter<<<(ETOT + 255) / 256, 256>>>(ei);

    k_gemm1<<<(N_ + 15) / 16, 256>>>(x, W1, as1, ad1);
    k_agg1<<<(N_ + 7) / 8, 256>>>(b1);

    k_gemm2<<<(N_ + 15) / 16, 256>>>(W2, as2, ad2);
    k_agg2<<<(N_ + 7) / 8, 256>>>(b2, out);
}

// round 4
// speedup vs baseline: 1.5125x; 1.2203x over previous
#include <cuda_runtime.h>
#include <math.h>

constexpr int N_   = 50000;
constexpr int E_   = 400000;
constexpr int ETOT = E_ + N_;   // edges + self loops
constexpr int SCAN_BLK = 1024;
constexpr int SCAN_NB  = (N_ + SCAN_BLK - 1) / SCAN_BLK;   // 49

// ---------------- scratch ---------------------------------------------------
__device__ __align__(16) float g_h1[N_ * 256];   // layer1 features [N,4,64]
__device__ __align__(16) float g_asrc1[N_ * 4];
__device__ __align__(16) float g_adst1[N_ * 4];
__device__ __align__(16) float g_x2[N_ * 64];    // layer1 out / layer2 in
__device__ __align__(16) float g_h2[N_ * 64];
__device__ float g_asrc2[N_];
__device__ float g_adst2[N_];
__device__ int   g_deg[N_];
__device__ int   g_rp[N_ + 1];
__device__ int   g_cursor[N_];
__device__ int   g_csr_src[ETOT];
__device__ int   g_bsum[SCAN_NB];
__device__ int   g_boff[SCAN_NB + 1];
__device__ int   g_is64;

// ---------------- helpers ---------------------------------------------------
__device__ __forceinline__ float lrelu(float x) { return x > 0.f ? x : 0.2f * x; }
__device__ __forceinline__ float eluf(float x)  { return x > 0.f ? x : expm1f(x); }

__device__ __forceinline__ int2 load_edge(const void* ei, int e) {
    int2 r;
    if (g_is64) {
        const long long* p = (const long long*)ei;
        r.x = (int)p[e]; r.y = (int)p[E_ + e];
    } else {
        const int* p = (const int*)ei;
        r.x = p[e]; r.y = p[E_ + e];
    }
    return r;
}

// ---------------- dtype detect + degree init -------------------------------
__global__ void k_detect(const unsigned int* __restrict__ ei) {
    if (threadIdx.x == 0) {
        int ok = 1;
        for (int i = 0; i < 32; i++)
            if (ei[2 * i + 1] != 0u) { ok = 0; break; }
        g_is64 = ok;
    }
}

__global__ void k_deginit() {
    int i = blockIdx.x * blockDim.x + threadIdx.x;
    if (i < N_) g_deg[i] = 1;          // self loop
}

__global__ void k_hist(const void* __restrict__ ei) {
    int e = blockIdx.x * blockDim.x + threadIdx.x;
    if (e >= E_) return;
    int2 sd = load_edge(ei, e);
    atomicAdd(&g_deg[sd.y], 1);
}

// ---------------- hierarchical exclusive scan ------------------------------
// phase 1: per-block scan; local exclusive -> g_rp, block sum -> g_bsum
__global__ void k_scan1() {
    __shared__ int swarp[32];
    int t = threadIdx.x;
    int gid = blockIdx.x * SCAN_BLK + t;
    int lane = t & 31, wid = t >> 5;
    int v = (gid < N_) ? g_deg[gid] : 0;
    int x = v;
    #pragma unroll
    for (int o = 1; o < 32; o <<= 1) {
        int y = __shfl_up_sync(0xffffffffu, x, o);
        if (lane >= o) x += y;
    }
    if (lane == 31) swarp[wid] = x;
    __syncthreads();
    if (wid == 0) {
        int y = swarp[lane];
        #pragma unroll
        for (int o = 1; o < 32; o <<= 1) {
            int z = __shfl_up_sync(0xffffffffu, y, o);
            if (lane >= o) y += z;
        }
        swarp[lane] = y;
    }
    __syncthreads();
    int woff = (wid > 0) ? swarp[wid - 1] : 0;
    int excl = woff + x - v;
    if (gid < N_) g_rp[gid] = excl;          // local exclusive, offset added later
    if (t == SCAN_BLK - 1) g_bsum[blockIdx.x] = woff + x;
}

// phase 2: scan block sums (SCAN_NB <= 64) in one warp-pair
__global__ void k_scan2() {
    int t = threadIdx.x;
    __shared__ int sm[64];
    int v = (t < SCAN_NB) ? g_bsum[t] : 0;
    sm[t] = v;
    __syncthreads();
    int x = v;
    #pragma unroll
    for (int o = 1; o < 64; o <<= 1) {
        int add = (t >= o) ? sm[t - o] : 0;
        __syncthreads();
        x += add; sm[t] = x;
        __syncthreads();
    }
    if (t < SCAN_NB) g_boff[t] = x - v;      // exclusive
    if (t == SCAN_NB - 1) g_boff[SCAN_NB] = x;
}

// phase 3: add block offsets, fill cursor, write total
__global__ void k_scan3() {
    int gid = blockIdx.x * blockDim.x + threadIdx.x;
    if (gid < N_) {
        int r = g_rp[gid] + g_boff[blockIdx.x * blockDim.x / SCAN_BLK + (threadIdx.x + blockIdx.x * blockDim.x) / SCAN_BLK - gid / SCAN_BLK + gid / SCAN_BLK];
        // simplified below; keep correct form:
        r = g_rp[gid] + g_boff[gid / SCAN_BLK];
        g_rp[gid] = r;
        g_cursor[gid] = r;
    }
    if (gid == 0) g_rp[N_] = g_boff[SCAN_NB];
}

__global__ void k_scatter(const void* __restrict__ ei) {
    int e = blockIdx.x * blockDim.x + threadIdx.x;
    if (e >= ETOT) return;
    int s, d;
    if (e < E_) { int2 sd = load_edge(ei, e); s = sd.x; d = sd.y; }
    else        { s = d = e - E_; }
    int pos = atomicAdd(&g_cursor[d], 1);
    g_csr_src[pos] = s;
}

// ---------------- layer 1: GEMM + attention logits -------------------------
__global__ void k_gemm1(const float* __restrict__ x, const float* __restrict__ W,
                        const float* __restrict__ as, const float* __restrict__ ad) {
    __shared__ float Ws[16 * 256];
    __shared__ float xs[16 * 16];
    __shared__ float rs[16 * 4];
    __shared__ float rd[16 * 4];
    int t = threadIdx.x;
    for (int i = t; i < 4096; i += 256) Ws[i] = W[i];
    int nb = blockIdx.x * 16;
    {
        int n = nb + (t >> 4);
        xs[t] = (n < N_) ? x[n * 16 + (t & 15)] : 0.f;
    }
    if (t < 64) { rs[t] = 0.f; rd[t] = 0.f; }
    float a_s = as[t], a_d = ad[t];
    __syncthreads();
    int head = t >> 6;
    for (int i = 0; i < 16; i++) {
        int n = nb + i;
        if (n >= N_) break;
        float acc = 0.f;
        #pragma unroll
        for (int k = 0; k < 16; k++) acc = fmaf(xs[i * 16 + k], Ws[k * 256 + t], acc);
        g_h1[n * 256 + t] = acc;
        float ps = acc * a_s, pd = acc * a_d;
        #pragma unroll
        for (int o = 16; o > 0; o >>= 1) {
            ps += __shfl_down_sync(0xffffffffu, ps, o);
            pd += __shfl_down_sync(0xffffffffu, pd, o);
        }
        if ((t & 31) == 0) {
            atomicAdd(&rs[i * 4 + head], ps);
            atomicAdd(&rd[i * 4 + head], pd);
        }
    }
    __syncthreads();
    if (t < 64) {
        int n = nb + (t >> 2);
        if (n < N_) {
            g_asrc1[n * 4 + (t & 3)] = rs[t];
            g_adst1[n * 4 + (t & 3)] = rd[t];
        }
    }
}

// ---------------- layer 2: GEMM + attention logits -------------------------
__global__ void k_gemm2(const float* __restrict__ W,
                        const float* __restrict__ as, const float* __restrict__ ad) {
    __shared__ float Ws[64 * 64];
    __shared__ float xs[16 * 65];
    __shared__ float rs[16];
    __shared__ float rd[16];
    int t = threadIdx.x;
    int col = t & 63;
    int g = t >> 6;
    for (int i = t; i < 4096; i += 256) Ws[i] = W[i];
    int nb = blockIdx.x * 16;
    for (int i = t; i < 1024; i += 256) {
        int n = nb + (i >> 6);
        xs[(i >> 6) * 65 + (i & 63)] = (n < N_) ? g_x2[n * 64 + (i & 63)] : 0.f;
    }
    if (t < 16) { rs[t] = 0.f; rd[t] = 0.f; }
    float a_s = as[col], a_d = ad[col];
    __syncthreads();
    for (int it = 0; it < 4; it++) {
        int i = it * 4 + g;
        int n = nb + i;
        float acc = 0.f;
        #pragma unroll
        for (int k = 0; k < 64; k++) acc = fmaf(xs[i * 65 + k], Ws[k * 64 + col], acc);
        if (n < N_) g_h2[n * 64 + col] = acc;
        float ps = acc * a_s, pd = acc * a_d;
        #pragma unroll
        for (int o = 16; o > 0; o >>= 1) {
            ps += __shfl_down_sync(0xffffffffu, ps, o);
            pd += __shfl_down_sync(0xffffffffu, pd, o);
        }
        if ((t & 31) == 0 && n < N_) {
            atomicAdd(&rs[i], ps);
            atomicAdd(&rd[i], pd);
        }
    }
    __syncthreads();
    if (t < 16) {
        int n = nb + t;
        if (n < N_) { g_asrc2[n] = rs[t]; g_adst2[n] = rd[t]; }
    }
}

// ---------------- layer 1 fused softmax-aggregate (warp per dst) -----------
__global__ void k_agg1(const float* __restrict__ b1) {
    __shared__ int    sm_s[8 * 32];
    __shared__ float4 sm_ex[8 * 32];
    int lane = threadIdx.x & 31;
    int w = threadIdx.x >> 5;
    int d = blockIdx.x * 8 + w;
    if (d >= N_) return;
    int rs = g_rp[d];
    int deg = g_rp[d + 1] - rs;
    float4 adst = *(const float4*)&g_adst1[d * 4];

    float4 m = make_float4(-1e30f, -1e30f, -1e30f, -1e30f);
    for (int base = 0; base < deg; base += 32) {
        int i = base + lane;
        if (i < deg) {
            int s = g_csr_src[rs + i];
            float4 a = *(const float4*)&g_asrc1[s * 4];
            m.x = fmaxf(m.x, lrelu(a.x + adst.x));
            m.y = fmaxf(m.y, lrelu(a.y + adst.y));
            m.z = fmaxf(m.z, lrelu(a.z + adst.z));
            m.w = fmaxf(m.w, lrelu(a.w + adst.w));
        }
    }
    #pragma unroll
    for (int o = 16; o > 0; o >>= 1) {
        m.x = fmaxf(m.x, __shfl_xor_sync(0xffffffffu, m.x, o));
        m.y = fmaxf(m.y, __shfl_xor_sync(0xffffffffu, m.y, o));
        m.z = fmaxf(m.z, __shfl_xor_sync(0xffffffffu, m.z, o));
        m.w = fmaxf(m.w, __shfl_xor_sync(0xffffffffu, m.w, o));
    }

    float4 den = make_float4(0.f, 0.f, 0.f, 0.f);
    float4 a0 = make_float4(0.f, 0.f, 0.f, 0.f);
    float4 a1 = make_float4(0.f, 0.f, 0.f, 0.f);
    int head = lane >> 3;
    for (int base = 0; base < deg; base += 32) {
        int i = base + lane;
        int s = -1;
        float4 ex = make_float4(0.f, 0.f, 0.f, 0.f);
        if (i < deg) {
            s = g_csr_src[rs + i];
            float4 a = *(const float4*)&g_asrc1[s * 4];
            ex.x = __expf(lrelu(a.x + adst.x) - m.x);
            ex.y = __expf(lrelu(a.y + adst.y) - m.y);
            ex.z = __expf(lrelu(a.z + adst.z) - m.z);
            ex.w = __expf(lrelu(a.w + adst.w) - m.w);
            den.x += ex.x; den.y += ex.y; den.z += ex.z; den.w += ex.w;
        }
        sm_s[w * 32 + lane] = s;
        sm_ex[w * 32 + lane] = ex;
        __syncwarp();
        int cnt = min(32, deg - base);
        const float* exb = (const float*)&sm_ex[w * 32];
        for (int j = 0; j < cnt; j++) {
            int sj = sm_s[w * 32 + j];
            float exj = exb[j * 4 + head];
            const float4* hp = (const float4*)&g_h1[sj * 256 + lane * 8];
            float4 v0 = hp[0], v1 = hp[1];
            a0.x = fmaf(exj, v0.x, a0.x); a0.y = fmaf(exj, v0.y, a0.y);
            a0.z = fmaf(exj, v0.z, a0.z); a0.w = fmaf(exj, v0.w, a0.w);
            a1.x = fmaf(exj, v1.x, a1.x); a1.y = fmaf(exj, v1.y, a1.y);
            a1.z = fmaf(exj, v1.z, a1.z); a1.w = fmaf(exj, v1.w, a1.w);
        }
        __syncwarp();
    }
    #pragma unroll
    for (int o = 16; o > 0; o >>= 1) {
        den.x += __shfl_xor_sync(0xffffffffu, den.x, o);
        den.y += __shfl_xor_sync(0xffffffffu, den.y, o);
        den.z += __shfl_xor_sync(0xffffffffu, den.z, o);
        den.w += __shfl_xor_sync(0xffffffffu, den.w, o);
    }
    float dh = (head == 0 ? den.x : head == 1 ? den.y : head == 2 ? den.z : den.w);
    float inv = 1.f / (dh + 1e-16f);
    a0.x *= inv; a0.y *= inv; a0.z *= inv; a0.w *= inv;
    a1.x *= inv; a1.y *= inv; a1.z *= inv; a1.w *= inv;
    #pragma unroll
    for (int o = 8; o <= 16; o <<= 1) {
        a0.x += __shfl_xor_sync(0xffffffffu, a0.x, o);
        a0.y += __shfl_xor_sync(0xffffffffu, a0.y, o);
        a0.z += __shfl_xor_sync(0xffffffffu, a0.z, o);
        a0.w += __shfl_xor_sync(0xffffffffu, a0.w, o);
        a1.x += __shfl_xor_sync(0xffffffffu, a1.x, o);
        a1.y += __shfl_xor_sync(0xffffffffu, a1.y, o);
        a1.z += __shfl_xor_sync(0xffffffffu, a1.z, o);
        a1.w += __shfl_xor_sync(0xffffffffu, a1.w, o);
    }
    if (lane < 8) {
        int c = lane * 8;
        float* o = &g_x2[d * 64 + c];
        o[0] = eluf(0.25f * a0.x + b1[c + 0]);
        o[1] = eluf(0.25f * a0.y + b1[c + 1]);
        o[2] = eluf(0.25f * a0.z + b1[c + 2]);
        o[3] = eluf(0.25f * a0.w + b1[c + 3]);
        o[4] = eluf(0.25f * a1.x + b1[c + 4]);
        o[5] = eluf(0.25f * a1.y + b1[c + 5]);
        o[6] = eluf(0.25f * a1.z + b1[c + 6]);
        o[7] = eluf(0.25f * a1.w + b1[c + 7]);
    }
}

// ---------------- layer 2 fused softmax-aggregate (warp per dst) -----------
__global__ void k_agg2(const float* __restrict__ b2, float* __restrict__ out) {
    __shared__ int   sm_s[8 * 32];
    __shared__ float sm_ex[8 * 32];
    int lane = threadIdx.x & 31;
    int w = threadIdx.x >> 5;
    int d = blockIdx.x * 8 + w;
    if (d >= N_) return;
    int rs = g_rp[d];
    int deg = g_rp[d + 1] - rs;
    float adst = g_adst2[d];

    float m = -1e30f;
    for (int base = 0; base < deg; base += 32) {
        int i = base + lane;
        if (i < deg) {
            int s = g_csr_src[rs + i];
            m = fmaxf(m, lrelu(g_asrc2[s] + adst));
        }
    }
    #pragma unroll
    for (int o = 16; o > 0; o >>= 1)
        m = fmaxf(m, __shfl_xor_sync(0xffffffffu, m, o));

    float den = 0.f;
    float2 acc = make_float2(0.f, 0.f);
    for (int base = 0; base < deg; base += 32) {
        int i = base + lane;
        int s = -1;
        float ex = 0.f;
        if (i < deg) {
            s = g_csr_src[rs + i];
            ex = __expf(lrelu(g_asrc2[s] + adst) - m);
            den += ex;
        }
        sm_s[w * 32 + lane] = s;
        sm_ex[w * 32 + lane] = ex;
        __syncwarp();
        int cnt = min(32, deg - base);
        for (int j = 0; j < cnt; j++) {
            int sj = sm_s[w * 32 + j];
            float exj = sm_ex[w * 32 + j];
            float2 v = *(const float2*)&g_h2[sj * 64 + lane * 2];
            acc.x = fmaf(exj, v.x, acc.x);
            acc.y = fmaf(exj, v.y, acc.y);
        }
        __syncwarp();
    }
    #pragma unroll
    for (int o = 16; o > 0; o >>= 1)
        den += __shfl_xor_sync(0xffffffffu, den, o);
    float inv = 1.f / (den + 1e-16f);
    int c = lane * 2;
    out[d * 64 + c + 0] = eluf(acc.x * inv + b2[c + 0]);
    out[d * 64 + c + 1] = eluf(acc.y * inv + b2[c + 1]);
}

// ---------------- launch ----------------------------------------------------
extern "C" void kernel_launch(void* const* d_in, const int* in_sizes, int n_in,
                              void* d_out, int out_size) {
    const float* x   = (const float*)d_in[0];
    const void*  ei  = d_in[1];
    const float* W1  = (const float*)d_in[2];
    const float* as1 = (const float*)d_in[3];
    const float* ad1 = (const float*)d_in[4];
    const float* b1  = (const float*)d_in[5];
    const float* W2  = (const float*)d_in[6];
    const float* as2 = (const float*)d_in[7];
    const float* ad2 = (const float*)d_in[8];
    const float* b2  = (const float*)d_in[9];
    float* out = (float*)d_out;

    k_detect<<<1, 32>>>((const unsigned int*)ei);
    k_deginit<<<(N_ + 255) / 256, 256>>>();
    k_hist<<<(E_ + 255) / 256, 256>>>(ei);
    k_scan1<<<SCAN_NB, SCAN_BLK>>>();
    k_scan2<<<1, 64>>>();
    k_scan3<<<SCAN_NB, SCAN_BLK>>>();
    k_scatter<<<(ETOT + 255) / 256, 256>>>(ei);

    k_gemm1<<<(N_ + 15) / 16, 256>>>(x, W1, as1, ad1);
    k_agg1<<<(N_ + 7) / 8, 256>>>(b1);

    k_gemm2<<<(N_ + 15) / 16, 256>>>(W2, as2, ad2);
    k_agg2<<<(N_ + 7) / 8, 256>>>(b2, out);
}

// round 5
// speedup vs baseline: 1.9439x; 1.2852x over previous
#include <cuda_runtime.h>
#include <math.h>

constexpr int N_   = 50000;
constexpr int E_   = 400000;
constexpr int ETOT = E_ + N_;   // edges + self loops
constexpr int SCAN_BLK = 1024;
constexpr int SCAN_NB  = (N_ + SCAN_BLK - 1) / SCAN_BLK;   // 49

// ---------------- scratch ---------------------------------------------------
__device__ __align__(16) float g_h1[N_ * 256];   // layer1 features [N,4,64]
__device__ __align__(16) float g_asrc1[N_ * 4];
__device__ __align__(16) float g_adst1[N_ * 4];
__device__ __align__(16) float g_x2[N_ * 64];    // layer1 out / layer2 in
__device__ __align__(16) float g_h2[N_ * 64];
__device__ float g_asrc2[N_];
__device__ float g_adst2[N_];
__device__ float g_vs1[16 * 4];
__device__ float g_vd1[16 * 4];
__device__ float g_vs2[64];
__device__ float g_vd2[64];
__device__ int   g_deg[N_];
__device__ int   g_rp[N_ + 1];
__device__ int   g_cursor[N_];
__device__ int   g_csr_src[ETOT];
__device__ int   g_bsum[SCAN_NB];
__device__ int   g_boff[SCAN_NB + 1];
__device__ int   g_is64;

// ---------------- helpers ---------------------------------------------------
__device__ __forceinline__ float lrelu(float x) { return x > 0.f ? x : 0.2f * x; }
__device__ __forceinline__ float eluf(float x)  { return x > 0.f ? x : expm1f(x); }

__device__ __forceinline__ int2 load_edge(const void* ei, int e) {
    int2 r;
    if (g_is64) {
        const long long* p = (const long long*)ei;
        r.x = (int)p[e]; r.y = (int)p[E_ + e];
    } else {
        const int* p = (const int*)ei;
        r.x = p[e]; r.y = p[E_ + e];
    }
    return r;
}

// ---------------- setup: detect dtype, init degrees, logit vectors ---------
__global__ void k_setup(const unsigned int* __restrict__ ei,
                        const float* __restrict__ W1,
                        const float* __restrict__ as1, const float* __restrict__ ad1,
                        const float* __restrict__ W2,
                        const float* __restrict__ as2, const float* __restrict__ ad2) {
    int i = blockIdx.x * blockDim.x + threadIdx.x;
    if (i < N_) g_deg[i] = 1;                      // self loop
    if (blockIdx.x == 0) {
        int t = threadIdx.x;
        if (t == 0) {
            int ok = 1;
            for (int k = 0; k < 32; k++)
                if (ei[2 * k + 1] != 0u) { ok = 0; break; }
            g_is64 = ok;
        }
        // v1[k][h] = sum_c W1[k,h*64+c] * att1[h,c]
        if (t < 64) {
            int k = t >> 2, h = t & 3;
            float s = 0.f, d = 0.f;
            for (int c = 0; c < 64; c++) {
                float w = W1[k * 256 + h * 64 + c];
                s = fmaf(w, as1[h * 64 + c], s);
                d = fmaf(w, ad1[h * 64 + c], d);
            }
            g_vs1[k * 4 + h] = s;
            g_vd1[k * 4 + h] = d;
        }
        // v2[k] = sum_c W2[k,c] * att2[c]
        if (t >= 64 && t < 128) {
            int k = t - 64;
            float s = 0.f, d = 0.f;
            for (int c = 0; c < 64; c++) {
                float w = W2[k * 64 + c];
                s = fmaf(w, as2[c], s);
                d = fmaf(w, ad2[c], d);
            }
            g_vs2[k] = s;
            g_vd2[k] = d;
        }
    }
}

__global__ void k_hist(const void* __restrict__ ei) {
    int e = blockIdx.x * blockDim.x + threadIdx.x;
    if (e >= E_) return;
    int2 sd = load_edge(ei, e);
    atomicAdd(&g_deg[sd.y], 1);
}

// ---------------- hierarchical exclusive scan ------------------------------
__global__ void k_scan1() {
    __shared__ int swarp[32];
    int t = threadIdx.x;
    int gid = blockIdx.x * SCAN_BLK + t;
    int lane = t & 31, wid = t >> 5;
    int v = (gid < N_) ? g_deg[gid] : 0;
    int x = v;
    #pragma unroll
    for (int o = 1; o < 32; o <<= 1) {
        int y = __shfl_up_sync(0xffffffffu, x, o);
        if (lane >= o) x += y;
    }
    if (lane == 31) swarp[wid] = x;
    __syncthreads();
    if (wid == 0) {
        int y = swarp[lane];
        #pragma unroll
        for (int o = 1; o < 32; o <<= 1) {
            int z = __shfl_up_sync(0xffffffffu, y, o);
            if (lane >= o) y += z;
        }
        swarp[lane] = y;
    }
    __syncthreads();
    int woff = (wid > 0) ? swarp[wid - 1] : 0;
    if (gid < N_) g_rp[gid] = woff + x - v;
    if (t == SCAN_BLK - 1) g_bsum[blockIdx.x] = woff + x;
}

__global__ void k_scan2() {
    int t = threadIdx.x;
    __shared__ int sm[64];
    int v = (t < SCAN_NB) ? g_bsum[t] : 0;
    sm[t] = v;
    __syncthreads();
    int x = v;
    #pragma unroll
    for (int o = 1; o < 64; o <<= 1) {
        int add = (t >= o) ? sm[t - o] : 0;
        __syncthreads();
        x += add; sm[t] = x;
        __syncthreads();
    }
    if (t < SCAN_NB) g_boff[t] = x - v;
    if (t == SCAN_NB - 1) g_boff[SCAN_NB] = x;
}

__global__ void k_scan3() {
    int gid = blockIdx.x * SCAN_BLK + threadIdx.x;
    if (gid < N_) {
        int r = g_rp[gid] + g_boff[blockIdx.x];
        g_rp[gid] = r;
        g_cursor[gid] = r;
    }
    if (gid == 0) g_rp[N_] = g_boff[SCAN_NB];
}

__global__ void k_scatter(const void* __restrict__ ei) {
    int e = blockIdx.x * blockDim.x + threadIdx.x;
    if (e >= ETOT) return;
    int s, d;
    if (e < E_) { int2 sd = load_edge(ei, e); s = sd.x; d = sd.y; }
    else        { s = d = e - E_; }
    int pos = atomicAdd(&g_cursor[d], 1);
    g_csr_src[pos] = s;
}

// ---------------- layer 1 GEMM: h1 = x @ W1 --------------------------------
__global__ void k_gemm1(const float* __restrict__ x, const float* __restrict__ W) {
    __shared__ float Ws[16 * 256];
    __shared__ float xs[16 * 16];
    int t = threadIdx.x;
    for (int i = t; i < 4096; i += 256) Ws[i] = W[i];
    int nb = blockIdx.x * 16;
    {
        int n = nb + (t >> 4);
        xs[t] = (n < N_) ? x[n * 16 + (t & 15)] : 0.f;
    }
    __syncthreads();
    #pragma unroll 4
    for (int i = 0; i < 16; i++) {
        int n = nb + i;
        if (n >= N_) break;
        float acc = 0.f;
        #pragma unroll
        for (int k = 0; k < 16; k++) acc = fmaf(xs[i * 16 + k], Ws[k * 256 + t], acc);
        g_h1[n * 256 + t] = acc;
    }
}

// ---------------- layer 1 logits: asrc1/adst1 = x @ v1 ---------------------
__global__ void k_logit1(const float* __restrict__ x) {
    __shared__ float vs[64], vd[64];
    if (threadIdx.x < 64) {
        vs[threadIdx.x] = g_vs1[threadIdx.x];
        vd[threadIdx.x] = g_vd1[threadIdx.x];
    }
    __syncthreads();
    int n = blockIdx.x * blockDim.x + threadIdx.x;
    if (n >= N_) return;
    const float4* xp = (const float4*)(x + n * 16);
    float4 xa = xp[0], xb = xp[1], xc = xp[2], xd = xp[3];
    float xv[16] = {xa.x, xa.y, xa.z, xa.w, xb.x, xb.y, xb.z, xb.w,
                    xc.x, xc.y, xc.z, xc.w, xd.x, xd.y, xd.z, xd.w};
    float s0 = 0, s1 = 0, s2 = 0, s3 = 0, d0 = 0, d1 = 0, d2 = 0, d3 = 0;
    #pragma unroll
    for (int k = 0; k < 16; k++) {
        float xk = xv[k];
        s0 = fmaf(xk, vs[k * 4 + 0], s0); d0 = fmaf(xk, vd[k * 4 + 0], d0);
        s1 = fmaf(xk, vs[k * 4 + 1], s1); d1 = fmaf(xk, vd[k * 4 + 1], d1);
        s2 = fmaf(xk, vs[k * 4 + 2], s2); d2 = fmaf(xk, vd[k * 4 + 2], d2);
        s3 = fmaf(xk, vs[k * 4 + 3], s3); d3 = fmaf(xk, vd[k * 4 + 3], d3);
    }
    *(float4*)&g_asrc1[n * 4] = make_float4(s0, s1, s2, s3);
    *(float4*)&g_adst1[n * 4] = make_float4(d0, d1, d2, d3);
}

// ---------------- layer 2 GEMM: h2 = x2 @ W2 -------------------------------
__global__ void k_gemm2(const float* __restrict__ W) {
    __shared__ float Ws[64 * 64];
    __shared__ float xs[16 * 65];
    int t = threadIdx.x;
    int col = t & 63;
    int g = t >> 6;
    for (int i = t; i < 4096; i += 256) Ws[i] = W[i];
    int nb = blockIdx.x * 16;
    for (int i = t; i < 1024; i += 256) {
        int n = nb + (i >> 6);
        xs[(i >> 6) * 65 + (i & 63)] = (n < N_) ? g_x2[n * 64 + (i & 63)] : 0.f;
    }
    __syncthreads();
    for (int it = 0; it < 4; it++) {
        int i = it * 4 + g;
        int n = nb + i;
        float acc = 0.f;
        #pragma unroll
        for (int k = 0; k < 64; k++) acc = fmaf(xs[i * 65 + k], Ws[k * 64 + col], acc);
        if (n < N_) g_h2[n * 64 + col] = acc;
    }
}

// ---------------- layer 1 fused softmax-aggregate (warp per dst) -----------
// Also emits layer-2 attention logits from the produced x2 row.
__global__ void k_agg1(const float* __restrict__ b1) {
    __shared__ int    sm_s[8 * 32];
    __shared__ float4 sm_ex[8 * 32];
    int lane = threadIdx.x & 31;
    int w = threadIdx.x >> 5;
    int d = blockIdx.x * 8 + w;
    if (d >= N_) return;
    int rsb = g_rp[d];
    int deg = g_rp[d + 1] - rsb;
    float4 adst = *(const float4*)&g_adst1[d * 4];
    int head = lane >> 3;

    float4 den = make_float4(0.f, 0.f, 0.f, 0.f);
    float4 a0 = make_float4(0.f, 0.f, 0.f, 0.f);
    float4 a1 = make_float4(0.f, 0.f, 0.f, 0.f);

    if (deg <= 32) {
        // ---- fast path: single gather, logits cached in registers ----
        int s = -1;
        float4 e = make_float4(-1e30f, -1e30f, -1e30f, -1e30f);
        if (lane < deg) {
            s = g_csr_src[rsb + lane];
            float4 a = *(const float4*)&g_asrc1[s * 4];
            e = make_float4(lrelu(a.x + adst.x), lrelu(a.y + adst.y),
                            lrelu(a.z + adst.z), lrelu(a.w + adst.w));
        }
        float4 m = e;
        #pragma unroll
        for (int o = 16; o > 0; o >>= 1) {
            m.x = fmaxf(m.x, __shfl_xor_sync(0xffffffffu, m.x, o));
            m.y = fmaxf(m.y, __shfl_xor_sync(0xffffffffu, m.y, o));
            m.z = fmaxf(m.z, __shfl_xor_sync(0xffffffffu, m.z, o));
            m.w = fmaxf(m.w, __shfl_xor_sync(0xffffffffu, m.w, o));
        }
        float4 ex = make_float4(0.f, 0.f, 0.f, 0.f);
        if (lane < deg) {
            ex = make_float4(__expf(e.x - m.x), __expf(e.y - m.y),
                             __expf(e.z - m.z), __expf(e.w - m.w));
            den = ex;
        }
        sm_s[w * 32 + lane] = s;
        sm_ex[w * 32 + lane] = ex;
        __syncwarp();
        const float* exb = (const float*)&sm_ex[w * 32];
        int j = 0;
        for (; j + 1 < deg; j += 2) {
            int sj0 = sm_s[w * 32 + j],     sj1 = sm_s[w * 32 + j + 1];
            float e0 = exb[j * 4 + head],   e1 = exb[(j + 1) * 4 + head];
            const float4* p0 = (const float4*)&g_h1[sj0 * 256 + lane * 8];
            const float4* p1 = (const float4*)&g_h1[sj1 * 256 + lane * 8];
            float4 u0 = p0[0], u1 = p0[1], v0 = p1[0], v1 = p1[1];
            a0.x = fmaf(e0, u0.x, a0.x); a0.y = fmaf(e0, u0.y, a0.y);
            a0.z = fmaf(e0, u0.z, a0.z); a0.w = fmaf(e0, u0.w, a0.w);
            a1.x = fmaf(e0, u1.x, a1.x); a1.y = fmaf(e0, u1.y, a1.y);
            a1.z = fmaf(e0, u1.z, a1.z); a1.w = fmaf(e0, u1.w, a1.w);
            a0.x = fmaf(e1, v0.x, a0.x); a0.y = fmaf(e1, v0.y, a0.y);
            a0.z = fmaf(e1, v0.z, a0.z); a0.w = fmaf(e1, v0.w, a0.w);
            a1.x = fmaf(e1, v1.x, a1.x); a1.y = fmaf(e1, v1.y, a1.y);
            a1.z = fmaf(e1, v1.z, a1.z); a1.w = fmaf(e1, v1.w, a1.w);
        }
        if (j < deg) {
            int sj = sm_s[w * 32 + j];
            float e0 = exb[j * 4 + head];
            const float4* p0 = (const float4*)&g_h1[sj * 256 + lane * 8];
            float4 u0 = p0[0], u1 = p0[1];
            a0.x = fmaf(e0, u0.x, a0.x); a0.y = fmaf(e0, u0.y, a0.y);
            a0.z = fmaf(e0, u0.z, a0.z); a0.w = fmaf(e0, u0.w, a0.w);
            a1.x = fmaf(e0, u1.x, a1.x); a1.y = fmaf(e0, u1.y, a1.y);
            a1.z = fmaf(e0, u1.z, a1.z); a1.w = fmaf(e0, u1.w, a1.w);
        }
    } else {
        // ---- generic two-pass path ----
        float4 m = make_float4(-1e30f, -1e30f, -1e30f, -1e30f);
        for (int base = 0; base < deg; base += 32) {
            int i = base + lane;
            if (i < deg) {
                int s = g_csr_src[rsb + i];
                float4 a = *(const float4*)&g_asrc1[s * 4];
                m.x = fmaxf(m.x, lrelu(a.x + adst.x));
                m.y = fmaxf(m.y, lrelu(a.y + adst.y));
                m.z = fmaxf(m.z, lrelu(a.z + adst.z));
                m.w = fmaxf(m.w, lrelu(a.w + adst.w));
            }
        }
        #pragma unroll
        for (int o = 16; o > 0; o >>= 1) {
            m.x = fmaxf(m.x, __shfl_xor_sync(0xffffffffu, m.x, o));
            m.y = fmaxf(m.y, __shfl_xor_sync(0xffffffffu, m.y, o));
            m.z = fmaxf(m.z, __shfl_xor_sync(0xffffffffu, m.z, o));
            m.w = fmaxf(m.w, __shfl_xor_sync(0xffffffffu, m.w, o));
        }
        for (int base = 0; base < deg; base += 32) {
            int i = base + lane;
            int s = -1;
            float4 ex = make_float4(0.f, 0.f, 0.f, 0.f);
            if (i < deg) {
                s = g_csr_src[rsb + i];
                float4 a = *(const float4*)&g_asrc1[s * 4];
                ex.x = __expf(lrelu(a.x + adst.x) - m.x);
                ex.y = __expf(lrelu(a.y + adst.y) - m.y);
                ex.z = __expf(lrelu(a.z + adst.z) - m.z);
                ex.w = __expf(lrelu(a.w + adst.w) - m.w);
                den.x += ex.x; den.y += ex.y; den.z += ex.z; den.w += ex.w;
            }
            sm_s[w * 32 + lane] = s;
            sm_ex[w * 32 + lane] = ex;
            __syncwarp();
            int cnt = min(32, deg - base);
            const float* exb = (const float*)&sm_ex[w * 32];
            for (int j = 0; j < cnt; j++) {
                int sj = sm_s[w * 32 + j];
                float exj = exb[j * 4 + head];
                const float4* hp = (const float4*)&g_h1[sj * 256 + lane * 8];
                float4 v0 = hp[0], v1 = hp[1];
                a0.x = fmaf(exj, v0.x, a0.x); a0.y = fmaf(exj, v0.y, a0.y);
                a0.z = fmaf(exj, v0.z, a0.z); a0.w = fmaf(exj, v0.w, a0.w);
                a1.x = fmaf(exj, v1.x, a1.x); a1.y = fmaf(exj, v1.y, a1.y);
                a1.z = fmaf(exj, v1.z, a1.z); a1.w = fmaf(exj, v1.w, a1.w);
            }
            __syncwarp();
        }
    }

    #pragma unroll
    for (int o = 16; o > 0; o >>= 1) {
        den.x += __shfl_xor_sync(0xffffffffu, den.x, o);
        den.y += __shfl_xor_sync(0xffffffffu, den.y, o);
        den.z += __shfl_xor_sync(0xffffffffu, den.z, o);
        den.w += __shfl_xor_sync(0xffffffffu, den.w, o);
    }
    float dh = (head == 0 ? den.x : head == 1 ? den.y : head == 2 ? den.z : den.w);
    float inv = 1.f / (dh + 1e-16f);
    a0.x *= inv; a0.y *= inv; a0.z *= inv; a0.w *= inv;
    a1.x *= inv; a1.y *= inv; a1.z *= inv; a1.w *= inv;
    #pragma unroll
    for (int o = 8; o <= 16; o <<= 1) {
        a0.x += __shfl_xor_sync(0xffffffffu, a0.x, o);
        a0.y += __shfl_xor_sync(0xffffffffu, a0.y, o);
        a0.z += __shfl_xor_sync(0xffffffffu, a0.z, o);
        a0.w += __shfl_xor_sync(0xffffffffu, a0.w, o);
        a1.x += __shfl_xor_sync(0xffffffffu, a1.x, o);
        a1.y += __shfl_xor_sync(0xffffffffu, a1.y, o);
        a1.z += __shfl_xor_sync(0xffffffffu, a1.z, o);
        a1.w += __shfl_xor_sync(0xffffffffu, a1.w, o);
    }
    if (lane < 8) {
        int c = lane * 8;
        float o0 = eluf(0.25f * a0.x + b1[c + 0]);
        float o1 = eluf(0.25f * a0.y + b1[c + 1]);
        float o2 = eluf(0.25f * a0.z + b1[c + 2]);
        float o3 = eluf(0.25f * a0.w + b1[c + 3]);
        float o4 = eluf(0.25f * a1.x + b1[c + 4]);
        float o5 = eluf(0.25f * a1.y + b1[c + 5]);
        float o6 = eluf(0.25f * a1.z + b1[c + 6]);
        float o7 = eluf(0.25f * a1.w + b1[c + 7]);
        float* op = &g_x2[d * 64 + c];
        op[0] = o0; op[1] = o1; op[2] = o2; op[3] = o3;
        op[4] = o4; op[5] = o5; op[6] = o6; op[7] = o7;
        // layer-2 attention logits fused here: asrc2[d] = x2[d,:] @ vs2
        float ps = o0 * g_vs2[c + 0] + o1 * g_vs2[c + 1] + o2 * g_vs2[c + 2] + o3 * g_vs2[c + 3]
                 + o4 * g_vs2[c + 4] + o5 * g_vs2[c + 5] + o6 * g_vs2[c + 6] + o7 * g_vs2[c + 7];
        float pd = o0 * g_vd2[c + 0] + o1 * g_vd2[c + 1] + o2 * g_vd2[c + 2] + o3 * g_vd2[c + 3]
                 + o4 * g_vd2[c + 4] + o5 * g_vd2[c + 5] + o6 * g_vd2[c + 6] + o7 * g_vd2[c + 7];
        #pragma unroll
        for (int o = 4; o > 0; o >>= 1) {
            ps += __shfl_xor_sync(0x000000ffu, ps, o);
            pd += __shfl_xor_sync(0x000000ffu, pd, o);
        }
        if (lane == 0) { g_asrc2[d] = ps; g_adst2[d] = pd; }
    }
}

// ---------------- layer 2 fused softmax-aggregate (warp per dst) -----------
__global__ void k_agg2(const float* __restrict__ b2, float* __restrict__ out) {
    __shared__ int   sm_s[8 * 32];
    __shared__ float sm_ex[8 * 32];
    int lane = threadIdx.x & 31;
    int w = threadIdx.x >> 5;
    int d = blockIdx.x * 8 + w;
    if (d >= N_) return;
    int rsb = g_rp[d];
    int deg = g_rp[d + 1] - rsb;
    float adst = g_adst2[d];

    float den = 0.f;
    float2 acc = make_float2(0.f, 0.f);

    if (deg <= 32) {
        int s = -1;
        float e = -1e30f;
        if (lane < deg) {
            s = g_csr_src[rsb + lane];
            e = lrelu(g_asrc2[s] + adst);
        }
        float m = e;
        #pragma unroll
        for (int o = 16; o > 0; o >>= 1)
            m = fmaxf(m, __shfl_xor_sync(0xffffffffu, m, o));
        float ex = 0.f;
        if (lane < deg) { ex = __expf(e - m); den = ex; }
        sm_s[w * 32 + lane] = s;
        sm_ex[w * 32 + lane] = ex;
        __syncwarp();
        int j = 0;
        for (; j + 1 < deg; j += 2) {
            int sj0 = sm_s[w * 32 + j], sj1 = sm_s[w * 32 + j + 1];
            float e0 = sm_ex[w * 32 + j], e1 = sm_ex[w * 32 + j + 1];
            float2 u = *(const float2*)&g_h2[sj0 * 64 + lane * 2];
            float2 v = *(const float2*)&g_h2[sj1 * 64 + lane * 2];
            acc.x = fmaf(e0, u.x, acc.x); acc.y = fmaf(e0, u.y, acc.y);
            acc.x = fmaf(e1, v.x, acc.x); acc.y = fmaf(e1, v.y, acc.y);
        }
        if (j < deg) {
            int sj = sm_s[w * 32 + j];
            float e0 = sm_ex[w * 32 + j];
            float2 u = *(const float2*)&g_h2[sj * 64 + lane * 2];
            acc.x = fmaf(e0, u.x, acc.x); acc.y = fmaf(e0, u.y, acc.y);
        }
    } else {
        float m = -1e30f;
        for (int base = 0; base < deg; base += 32) {
            int i = base + lane;
            if (i < deg) {
                int s = g_csr_src[rsb + i];
                m = fmaxf(m, lrelu(g_asrc2[s] + adst));
            }
        }
        #pragma unroll
        for (int o = 16; o > 0; o >>= 1)
            m = fmaxf(m, __shfl_xor_sync(0xffffffffu, m, o));
        for (int base = 0; base < deg; base += 32) {
            int i = base + lane;
            int s = -1;
            float ex = 0.f;
            if (i < deg) {
                s = g_csr_src[rsb + i];
                ex = __expf(lrelu(g_asrc2[s] + adst) - m);
                den += ex;
            }
            sm_s[w * 32 + lane] = s;
            sm_ex[w * 32 + lane] = ex;
            __syncwarp();
            int cnt = min(32, deg - base);
            for (int j = 0; j < cnt; j++) {
                int sj = sm_s[w * 32 + j];
                float exj = sm_ex[w * 32 + j];
                float2 v = *(const float2*)&g_h2[sj * 64 + lane * 2];
                acc.x = fmaf(exj, v.x, acc.x);
                acc.y = fmaf(exj, v.y, acc.y);
            }
            __syncwarp();
        }
    }
    #pragma unroll
    for (int o = 16; o > 0; o >>= 1)
        den += __shfl_xor_sync(0xffffffffu, den, o);
    float inv = 1.f / (den + 1e-16f);
    int c = lane * 2;
    out[d * 64 + c + 0] = eluf(acc.x * inv + b2[c + 0]);
    out[d * 64 + c + 1] = eluf(acc.y * inv + b2[c + 1]);
}

// ---------------- launch ----------------------------------------------------
extern "C" void kernel_launch(void* const* d_in, const int* in_sizes, int n_in,
                              void* d_out, int out_size) {
    const float* x   = (const float*)d_in[0];
    const void*  ei  = d_in[1];
    const float* W1  = (const float*)d_in[2];
    const float* as1 = (const float*)d_in[3];
    const float* ad1 = (const float*)d_in[4];
    const float* b1  = (const float*)d_in[5];
    const float* W2  = (const float*)d_in[6];
    const float* as2 = (const float*)d_in[7];
    const float* ad2 = (const float*)d_in[8];
    const float* b2  = (const float*)d_in[9];
    float* out = (float*)d_out;

    k_setup<<<(N_ + 255) / 256, 256>>>((const unsigned int*)ei, W1, as1, ad1, W2, as2, ad2);
    k_hist<<<(E_ + 255) / 256, 256>>>(ei);
    k_scan1<<<SCAN_NB, SCAN_BLK>>>();
    k_scan2<<<1, 64>>>();
    k_scan3<<<SCAN_NB, SCAN_BLK>>>();
    k_scatter<<<(ETOT + 255) / 256, 256>>>(ei);

    k_gemm1<<<(N_ + 15) / 16, 256>>>(x, W1);
    k_logit1<<<(N_ + 255) / 256, 256>>>(x);
    k_agg1<<<(N_ + 7) / 8, 256>>>(b1);

    k_gemm2<<<(N_ + 15) / 16, 256>>>(W2);
    k_agg2<<<(N_ + 7) / 8, 256>>>(b2, out);
}